// round 1
// baseline (speedup 1.0000x reference)
#include <cuda_runtime.h>
#include <cstdint>

// Problem constants
#define NN 4096
#define FF 128
#define HID 128
#define HEADS 8
#define HDIM 16
#define CC 64
#define EE 131072

// ---------------- scratch (no allocation allowed) ----------------
__device__ float g_H[NN * HID];     // GEMM output of X@W (pre-scatter)
__device__ float g_G[NN * HID];     // conv output (reused conv1/conv2)
__device__ float g_QKV[NN * 3 * FF];
__device__ float g_O[NN * FF];      // attention output
__device__ float g_TF[NN * FF];     // after out_proj
__device__ float g_GNN[NN * CC];    // gnn branch output
__device__ float g_deg[NN];
__device__ float g_dinv[NN];

// ---------------- small elementwise kernels ----------------
__global__ void deg_init_kernel(float* deg) {
    int i = blockIdx.x * blockDim.x + threadIdx.x;
    if (i < NN) deg[i] = 1.0f;   // self loop
}

__global__ void deg_count_kernel(const int* col, float* deg) {
    int e = blockIdx.x * blockDim.x + threadIdx.x;
    if (e < EE) atomicAdd(&deg[col[e]], 1.0f);
}

__global__ void dinv_kernel(const float* deg, float* dinv) {
    int i = blockIdx.x * blockDim.x + threadIdx.x;
    if (i < NN) dinv[i] = rsqrtf(deg[i]);
}

// out[i,f] = b[f] + H[i,f] * dinv[i]^2   (self-loop message + bias)
__global__ void self_init_kernel(const float* __restrict__ H,
                                 const float* __restrict__ dinv,
                                 const float* __restrict__ b,
                                 float* __restrict__ out) {
    int gid = blockIdx.x * blockDim.x + threadIdx.x;
    if (gid >= NN * HID) return;
    int i = gid >> 7;      // /128
    int f = gid & 127;
    float d = dinv[i];
    out[gid] = b[f] + H[gid] * d * d;
}

__global__ void relu_kernel(float* x, int n) {
    int gid = blockIdx.x * blockDim.x + threadIdx.x;
    if (gid < n) x[gid] = fmaxf(x[gid], 0.0f);
}

// ---------------- edge scatter: out[col] += H[row] * dinv[row]*dinv[col] ----
// one warp per edge, each lane handles 4 floats via red.v4
__global__ void scatter_kernel(const float* __restrict__ H,
                               const int* __restrict__ row,
                               const int* __restrict__ col,
                               const float* __restrict__ dinv,
                               float* __restrict__ out) {
    int gid = blockIdx.x * blockDim.x + threadIdx.x;
    int e = gid >> 5;
    if (e >= EE) return;
    int lane = gid & 31;
    int r = row[e];
    int c = col[e];
    float w = dinv[r] * dinv[c];
    float4 hv = *(const float4*)(H + r * HID + lane * 4);
    float* dst = out + c * HID + lane * 4;
    asm volatile("red.global.add.v4.f32 [%0], {%1, %2, %3, %4};"
                 :: "l"(dst), "f"(hv.x * w), "f"(hv.y * w), "f"(hv.z * w), "f"(hv.w * w)
                 : "memory");
}

// ---------------- tiled SGEMM ----------------
// C[M,N] = A[M,K] @ B (+bias)(+add)(relu)
// TRANSB=false: B is [K,N];  TRANSB=true: B is [N,K] (weight.T multiply)
// Requires M%64==0, N%64==0, K%16==0 (always true here).
template <bool TRANSB>
__global__ __launch_bounds__(256)
void sgemm_kernel(const float* __restrict__ A, const float* __restrict__ B,
                  const float* __restrict__ bias, const float* __restrict__ add,
                  float* __restrict__ C, int M, int N, int K, int do_relu) {
    const int BM = 64, BN = 64, BK = 16;
    __shared__ float As[BK][BM];
    __shared__ float Bs[BK][BN];

    int tid = threadIdx.x;
    int tx = tid & 15;        // 0..15 -> col group
    int ty = tid >> 4;        // 0..15 -> row group
    int m0 = blockIdx.y * BM;
    int n0 = blockIdx.x * BN;

    float acc[4][4];
    #pragma unroll
    for (int i = 0; i < 4; i++)
        #pragma unroll
        for (int j = 0; j < 4; j++) acc[i][j] = 0.0f;

    for (int k0 = 0; k0 < K; k0 += BK) {
        // load A tile 64x16: one float4 per thread
        {
            int arow = tid >> 2;            // 0..63
            int acol = (tid & 3) * 4;       // 0,4,8,12
            float4 a = *(const float4*)(A + (m0 + arow) * K + k0 + acol);
            As[acol + 0][arow] = a.x;
            As[acol + 1][arow] = a.y;
            As[acol + 2][arow] = a.z;
            As[acol + 3][arow] = a.w;
        }
        // load B tile
        if (!TRANSB) {
            int brow = tid >> 4;            // 0..15
            int bcol = (tid & 15) * 4;      // 0..60
            float4 b = *(const float4*)(B + (k0 + brow) * N + n0 + bcol);
            *(float4*)&Bs[brow][bcol] = b;
        } else {
            int bn = tid >> 2;              // 0..63
            int bk = (tid & 3) * 4;         // 0,4,8,12
            float4 b = *(const float4*)(B + (n0 + bn) * K + k0 + bk);
            Bs[bk + 0][bn] = b.x;
            Bs[bk + 1][bn] = b.y;
            Bs[bk + 2][bn] = b.z;
            Bs[bk + 3][bn] = b.w;
        }
        __syncthreads();

        #pragma unroll
        for (int kk = 0; kk < BK; kk++) {
            float4 av = *(const float4*)&As[kk][ty * 4];
            float4 bv = *(const float4*)&Bs[kk][tx * 4];
            float a[4] = {av.x, av.y, av.z, av.w};
            float b[4] = {bv.x, bv.y, bv.z, bv.w};
            #pragma unroll
            for (int i = 0; i < 4; i++)
                #pragma unroll
                for (int j = 0; j < 4; j++)
                    acc[i][j] += a[i] * b[j];
        }
        __syncthreads();
    }

    // epilogue
    #pragma unroll
    for (int i = 0; i < 4; i++) {
        int r = m0 + ty * 4 + i;
        int cbase = n0 + tx * 4;
        float4 v;
        float* vp = &v.x;
        #pragma unroll
        for (int j = 0; j < 4; j++) {
            float x = acc[i][j];
            if (bias) x += bias[cbase + j];
            if (add)  x += add[r * N + cbase + j];
            if (do_relu) x = fmaxf(x, 0.0f);
            vp[j] = x;
        }
        *(float4*)(C + r * N + cbase) = v;
    }
}

// ---------------- flash attention ----------------
// 8 heads, head_dim=16, N=4096 keys. 1 query per thread, 128 queries/block.
// Key/value tiles of 32 staged in shared memory.
__global__ __launch_bounds__(128)
void attn_kernel(const float* __restrict__ QKV, float* __restrict__ O) {
    const int h = blockIdx.y;
    const int t = threadIdx.x;
    const int qi = blockIdx.x * 128 + t;

    __shared__ float Ks[32][16];
    __shared__ float Vs[32][16];

    float q[16];
    {
        const float4* qrow = (const float4*)(QKV + qi * (3 * FF) + h * HDIM);
        #pragma unroll
        for (int d4 = 0; d4 < 4; d4++) {
            float4 v = qrow[d4];
            q[d4 * 4 + 0] = v.x; q[d4 * 4 + 1] = v.y;
            q[d4 * 4 + 2] = v.z; q[d4 * 4 + 3] = v.w;
        }
    }

    float m = -1e30f, l = 0.0f;
    float o[16];
    #pragma unroll
    for (int d = 0; d < 16; d++) o[d] = 0.0f;

    const float scale = 0.25f;  // 1/sqrt(16)

    for (int k0 = 0; k0 < NN; k0 += 32) {
        __syncthreads();
        {
            int j = t >> 2;             // 0..31
            int p = (t & 3) * 4;        // 0,4,8,12
            const float* base = QKV + (k0 + j) * (3 * FF) + h * HDIM + p;
            *(float4*)&Ks[j][p] = *(const float4*)(base + FF);
            *(float4*)&Vs[j][p] = *(const float4*)(base + 2 * FF);
        }
        __syncthreads();

        float s[32];
        float tmax = -1e30f;
        #pragma unroll
        for (int j = 0; j < 32; j++) {
            float acc = 0.0f;
            #pragma unroll
            for (int d4 = 0; d4 < 4; d4++) {
                float4 kv = *(const float4*)&Ks[j][d4 * 4];
                acc += q[d4 * 4 + 0] * kv.x;
                acc += q[d4 * 4 + 1] * kv.y;
                acc += q[d4 * 4 + 2] * kv.z;
                acc += q[d4 * 4 + 3] * kv.w;
            }
            s[j] = acc * scale;
            tmax = fmaxf(tmax, s[j]);
        }

        float mnew = fmaxf(m, tmax);
        float corr = __expf(m - mnew);
        l *= corr;
        #pragma unroll
        for (int d = 0; d < 16; d++) o[d] *= corr;

        #pragma unroll
        for (int j = 0; j < 32; j++) {
            float p = __expf(s[j] - mnew);
            l += p;
            #pragma unroll
            for (int d4 = 0; d4 < 4; d4++) {
                float4 vv = *(const float4*)&Vs[j][d4 * 4];
                o[d4 * 4 + 0] += p * vv.x;
                o[d4 * 4 + 1] += p * vv.y;
                o[d4 * 4 + 2] += p * vv.z;
                o[d4 * 4 + 3] += p * vv.w;
            }
        }
        m = mnew;
    }

    float inv = 1.0f / l;
    float* orow = O + qi * FF + h * HDIM;
    #pragma unroll
    for (int d4 = 0; d4 < 4; d4++) {
        float4 v;
        v.x = o[d4 * 4 + 0] * inv;
        v.y = o[d4 * 4 + 1] * inv;
        v.z = o[d4 * 4 + 2] * inv;
        v.w = o[d4 * 4 + 3] * inv;
        *(float4*)(orow + d4 * 4) = v;
    }
}

// ---------------- launch ----------------
extern "C" void kernel_launch(void* const* d_in, const int* in_sizes, int n_in,
                              void* d_out, int out_size) {
    const float* x          = (const float*)d_in[0];
    const int*   edge_index = (const int*)  d_in[1];
    const float* W1         = (const float*)d_in[2];
    const float* b1         = (const float*)d_in[3];
    const float* W2         = (const float*)d_in[4];
    const float* b2         = (const float*)d_in[5];
    const float* W3         = (const float*)d_in[6];
    const float* b3         = (const float*)d_in[7];
    const float* in_w       = (const float*)d_in[8];
    const float* in_b       = (const float*)d_in[9];
    const float* out_w      = (const float*)d_in[10];
    const float* out_b      = (const float*)d_in[11];
    const float* proj_w     = (const float*)d_in[12];
    const float* proj_b     = (const float*)d_in[13];
    float* out = (float*)d_out;

    const int* row = edge_index;
    const int* col = edge_index + EE;

    float *H, *G, *QKV, *O, *TF, *GNN, *deg, *dinv;
    cudaGetSymbolAddress((void**)&H,   g_H);
    cudaGetSymbolAddress((void**)&G,   g_G);
    cudaGetSymbolAddress((void**)&QKV, g_QKV);
    cudaGetSymbolAddress((void**)&O,   g_O);
    cudaGetSymbolAddress((void**)&TF,  g_TF);
    cudaGetSymbolAddress((void**)&GNN, g_GNN);
    cudaGetSymbolAddress((void**)&deg, g_deg);
    cudaGetSymbolAddress((void**)&dinv,g_dinv);

    // degree / normalization
    deg_init_kernel<<<(NN + 255) / 256, 256>>>(deg);
    deg_count_kernel<<<(EE + 255) / 256, 256>>>(col, deg);
    dinv_kernel<<<(NN + 255) / 256, 256>>>(deg, dinv);

    // ---- GCN conv 1 ----
    sgemm_kernel<false><<<dim3(HID / 64, NN / 64), 256>>>(x, W1, nullptr, nullptr, H, NN, HID, FF, 0);
    self_init_kernel<<<(NN * HID + 255) / 256, 256>>>(H, dinv, b1, G);
    scatter_kernel<<<(EE * 32 + 255) / 256, 256>>>(H, row, col, dinv, G);
    relu_kernel<<<(NN * HID + 255) / 256, 256>>>(G, NN * HID);

    // ---- GCN conv 2 ----
    sgemm_kernel<false><<<dim3(HID / 64, NN / 64), 256>>>(G, W2, nullptr, nullptr, H, NN, HID, HID, 0);
    self_init_kernel<<<(NN * HID + 255) / 256, 256>>>(H, dinv, b2, G);
    scatter_kernel<<<(EE * 32 + 255) / 256, 256>>>(H, row, col, dinv, G);
    relu_kernel<<<(NN * HID + 255) / 256, 256>>>(G, NN * HID);

    // ---- GNN head: GNN = G @ W3 + b3 ----
    sgemm_kernel<false><<<dim3(CC / 64, NN / 64), 256>>>(G, W3, b3, nullptr, GNN, NN, CC, HID, 0);

    // ---- Transformer branch ----
    // QKV = x @ in_w.T + in_b   [4096, 384]
    sgemm_kernel<true><<<dim3(3 * FF / 64, NN / 64), 256>>>(x, in_w, in_b, nullptr, QKV, NN, 3 * FF, FF, 0);
    // attention -> O [4096, 128]
    attn_kernel<<<dim3(NN / 128, HEADS), 128>>>(QKV, O);
    // TF = O @ out_w.T + out_b
    sgemm_kernel<true><<<dim3(FF / 64, NN / 64), 256>>>(O, out_w, out_b, nullptr, TF, NN, FF, FF, 0);
    // out = relu(TF @ proj_w + proj_b + GNN)
    sgemm_kernel<false><<<dim3(CC / 64, NN / 64), 256>>>(TF, proj_w, proj_b, GNN, out, NN, CC, FF, 1);
}